// round 16
// baseline (speedup 1.0000x reference)
#include <cuda_runtime.h>
#include <math.h>
#include <mma.h>

using namespace nvcuda;

// Problem constants
#define NB 4          // batch
#define NM 32         // masks (sam_masks[:,1:])
#define C2 1024       // channels of layer 2
#define P2 1024       // 32*32 pixels of layer 2
#define HMASK 512     // sam mask resolution
#define NR 128        // NB*NM rows
#define KS 16         // K-splits in qgemm (KC=64)
#define NPC 8         // pixel chunks in pooling (128 px each)

// Output layout: out0 | out1 | out2 (floats)
#define OFF1 16777216L   // 4*256*128*128
#define OFF2 25165824L   // OFF1 + 4*512*64*64
#define TOT  29360128L   // OFF2 + 4*1024*32*32

// -------- scratch (device globals; no allocation allowed) --------
__device__ int   g_idx[NB*P2];             // mask id per sampled pixel, -1 if none
__device__ float g_mfpart[NB*NPC*NM*C2];   // raw pooling partials (4MB, L2)
__device__ float g_mf0[NR*C2];             // normalized mask features (= mf' * beta)
__device__ float g_qpart[KS*NR*C2];        // q GEMM K-split partials (8MB)
__device__ float g_q[NR*C2];               // q = beta*(mf' @ W^T) + b
__device__ float g_qn[NR];                 // ||q_row||
__device__ float g_gp[NR*C2];              // graph-attn output (unnormalized)
__device__ float g_scale[NR];              // sigmoid(g)/max(||gp||,1e-12)

// -------- K1: pooling with FUSED idx computation --------
__global__ void k_mfpart(const int* __restrict__ sam,
                         const float* __restrict__ feat2) {
    int b = blockIdx.x, ct = blockIdx.y, pc = blockIdx.z;  // (4,4,8)
    int t = threadIdx.x;                 // 256, thread = one channel
    int c = ct*256 + t;
    __shared__ float sbins[NM*256];      // [m*256+t]: bank = t%32, conflict-free
    __shared__ int   sidx[128];
    #pragma unroll
    for (int m = 0; m < NM; m++) sbins[m*256 + t] = 0.f;
    if (t < 128) sidx[t] = -1;
    __syncthreads();
    // idx for the 128 pixels of this chunk (shared atomicMax = deterministic)
    #pragma unroll
    for (int i = 0; i < 16; i++) {
        int task = i*256 + t;            // p = task&127, m = task>>7
        int p = task & 127, m = task >> 7;
        int pix = pc*128 + p;
        int y = pix >> 5, x = pix & 31;
        long off = ((long)b*33 + (m+1))*HMASK*HMASK + (long)(y*16)*HMASK + (long)(x*16);
        if (__ldg(sam + off) == 1) atomicMax(&sidx[p], m);
    }
    __syncthreads();
    if (ct == 0 && t < 128) g_idx[b*P2 + pc*128 + t] = sidx[t];
    const float4* fp = (const float4*)(feat2 + ((long)b*C2 + c)*P2 + pc*128);
    #pragma unroll 4
    for (int i = 0; i < 32; i++) {
        float4 v = fp[i];
        int p0 = i*4;
        int m0 = sidx[p0+0], m1 = sidx[p0+1], m2 = sidx[p0+2], m3 = sidx[p0+3];
        if (m0 >= 0) sbins[m0*256 + t] += v.x;
        if (m1 >= 0) sbins[m1*256 + t] += v.y;
        if (m2 >= 0) sbins[m2*256 + t] += v.z;
        if (m3 >= 0) sbins[m3*256 + t] += v.w;
    }
    #pragma unroll
    for (int m = 0; m < NM; m++)
        g_mfpart[((b*NPC + pc)*NM + m)*C2 + c] = sbins[m*256 + t];
}

// -------- K2: q' GEMM on RAW mf' via TF32 tensor cores (wmma m16n16k8) -----
// grid (16 cb, 16 ks) = 256 blocks x 256 thr (8 warps). Block computes the
// 128-row x 64-col x 64-K tile. A (mf' = sum of partials) staged to smem as
// tf32; B = W^T read DIRECTLY from global W via col_major fragment (W is
// [c][k] row-major => element (k, n) at W[n*1024 + k], ldm = 1024).
#define ALD 72   // A smem leading dim (mult of 4; strips 16B-aligned)
__global__ void __launch_bounds__(256)
k_qgemm(const float* __restrict__ W) {
    int cb = blockIdx.x, ks = blockIdx.y;
    int t = threadIdx.x;
    int w = t >> 5;                            // 8 warps
    int k0 = ks*64;
    __shared__ float sA[128*ALD];              // ~36.9KB, tf32-converted
    #pragma unroll
    for (int it = 0; it < 8; it++) {
        int task = it*256 + t;                 // row 0..127, k4 0..15
        int row = task & 127, k4 = task >> 7;
        int bb = row >> 5, mm = row & 31;
        float4 v = make_float4(0.f, 0.f, 0.f, 0.f);
        #pragma unroll
        for (int pc = 0; pc < NPC; pc++) {
            float4 p = *(const float4*)(g_mfpart + ((long)(bb*NPC + pc)*NM + mm)*C2 + k0 + k4*4);
            v.x += p.x; v.y += p.y; v.z += p.z; v.w += p.w;
        }
        float* d = sA + row*ALD + k4*4;
        d[0] = wmma::__float_to_tf32(v.x);
        d[1] = wmma::__float_to_tf32(v.y);
        d[2] = wmma::__float_to_tf32(v.z);
        d[3] = wmma::__float_to_tf32(v.w);
    }
    __syncthreads();
    wmma::fragment<wmma::accumulator, 16, 16, 8, float> fc[4];
    #pragma unroll
    for (int n = 0; n < 4; n++) wmma::fill_fragment(fc[n], 0.f);
    int row0 = w*16;
    for (int kk = 0; kk < 64; kk += 8) {
        wmma::fragment<wmma::matrix_a, 16, 16, 8, wmma::precision::tf32, wmma::row_major> fa;
        wmma::load_matrix_sync(fa, sA + row0*ALD + kk, ALD);
        #pragma unroll
        for (int n = 0; n < 4; n++) {
            wmma::fragment<wmma::matrix_b, 16, 16, 8, wmma::precision::tf32, wmma::col_major> fb;
            wmma::load_matrix_sync(fb, W + (long)(cb*64 + n*16)*C2 + k0 + kk, C2);
            #pragma unroll
            for (int i = 0; i < fb.num_elements; i++)
                fb.x[i] = wmma::__float_to_tf32(fb.x[i]);
            wmma::mma_sync(fc[n], fa, fb, fc[n]);
        }
    }
    #pragma unroll
    for (int n = 0; n < 4; n++)
        wmma::store_matrix_sync(g_qpart + ((long)ks*NR + row0)*C2 + cb*64 + n*16,
                                fc[n], C2, wmma::mem_row_major);
}

// -------- K3: per-row cnt, beta, mf0, q = beta*sum(qpart)+bias, qn --------
__global__ void k_qreduce(const float* __restrict__ bias) {
    int row = blockIdx.x, t = threadIdx.x;   // 128 blocks x 256
    int b = row >> 5, m = row & 31;
    int w = t >> 5, l = t & 31;
    __shared__ float sw8[8];
    const int* ip = g_idx + b*P2;
    int cnt = 0;
    #pragma unroll
    for (int j = 0; j < 4; j++) cnt += (ip[t + j*256] == m);
    float fc = (float)cnt;
    #pragma unroll
    for (int o = 16; o; o >>= 1) fc += __shfl_xor_sync(0xffffffffu, fc, o);
    if (l == 0) sw8[w] = fc;
    __syncthreads();
    float tot = 0.f;
    #pragma unroll
    for (int i = 0; i < 8; i++) tot += sw8[i];
    float inv = 1.f / (tot + 1e-5f);
    __syncthreads();
    float mfv[4]; float sq = 0.f;
    #pragma unroll
    for (int j = 0; j < 4; j++) {
        int c = t + j*256;
        float v = 0.f;
        #pragma unroll
        for (int pc = 0; pc < NPC; pc++)
            v += g_mfpart[((long)(b*NPC + pc)*NM + m)*C2 + c];
        mfv[j] = v;
        sq += v*v;
    }
    #pragma unroll
    for (int o = 16; o; o >>= 1) sq += __shfl_xor_sync(0xffffffffu, sq, o);
    if (l == 0) sw8[w] = sq;
    __syncthreads();
    float s2 = 0.f;
    #pragma unroll
    for (int i = 0; i < 8; i++) s2 += sw8[i];
    float beta = inv / fmaxf(inv*sqrtf(s2), 1e-12f);   // exact l2norm algebra
    __syncthreads();
    float sqq = 0.f;
    #pragma unroll
    for (int j = 0; j < 4; j++) {
        int c = t + j*256;
        g_mf0[(long)row*C2 + c] = mfv[j]*beta;
        float v = 0.f;
        #pragma unroll
        for (int ks = 0; ks < KS; ks++)
            v += g_qpart[((long)ks*NR + row)*C2 + c];
        v = beta*v + bias[c];
        sqq += v*v;
        g_q[(long)row*C2 + c] = v;
    }
    #pragma unroll
    for (int o = 16; o; o >>= 1) sqq += __shfl_xor_sync(0xffffffffu, sqq, o);
    if (l == 0) sw8[w] = sqq;
    __syncthreads();
    if (t == 0) {
        float n2 = 0.f;
        #pragma unroll
        for (int i = 0; i < 8; i++) n2 += sw8[i];
        g_qn[row] = sqrtf(n2);
    }
}

// -------- K4: fused edge row + gp row + gate scale. 1024 threads/block -----
__global__ void __launch_bounds__(1024)
k_attn2(const float* __restrict__ gate) {
    int b = blockIdx.x, i = blockIdx.y, t = threadIdx.x;
    int w = t >> 5, l = t & 31;                 // 32 warps
    __shared__ float sdot[NM];
    __shared__ float se[NM];
    __shared__ float sw32[32];
    {
        const float4* qi = (const float4*)(g_q + (long)(b*NM + i)*C2);
        const float4* qj = (const float4*)(g_q + (long)(b*NM + w)*C2);
        float part = 0.f;
        #pragma unroll
        for (int k = 0; k < 8; k++) {
            float4 a = qi[k*32 + l], bb = qj[k*32 + l];
            part += a.x*bb.x + a.y*bb.y + a.z*bb.z + a.w*bb.w;
        }
        #pragma unroll
        for (int o = 16; o; o >>= 1) part += __shfl_xor_sync(0xffffffffu, part, o);
        if (l == 0) sdot[w] = part;
    }
    __syncthreads();
    if (t < NM) {
        float sim = sdot[t] / (g_qn[b*NM + i]*g_qn[b*NM + t] + 1e-8f);
        float rs = sim;
        #pragma unroll
        for (int o = 16; o; o >>= 1) rs += __shfl_xor_sync(0xffffffffu, rs, o);
        se[t] = sim / (rs + 1e-8f);
    }
    __syncthreads();
    float acc = 0.f;
    #pragma unroll 8
    for (int n = 0; n < NM; n++)
        acc += se[n] * g_q[(long)(b*NM + n)*C2 + t];
    g_gp[(long)(b*NM + i)*C2 + t] = acc;
    float sq = acc*acc;
    #pragma unroll
    for (int o = 16; o; o >>= 1) sq += __shfl_xor_sync(0xffffffffu, sq, o);
    if (l == 0) sw32[w] = sq;
    __syncthreads();
    if (t == 0) {
        float s2 = 0.f;
        #pragma unroll
        for (int k = 0; k < 32; k++) s2 += sw32[k];   // fixed order
        float sg = 1.f / (1.f + expf(-gate[0]));
        g_scale[b*NM + i] = sg / fmaxf(sqrtf(s2), 1e-12f);
    }
}

// -------- K5: copies + out2 gather; ILP-4, block-uniform region branch -----
__global__ void k_final(const float* __restrict__ f0,
                        const float* __restrict__ f1,
                        const float* __restrict__ f2,
                        float* __restrict__ out) {
    int bid = blockIdx.x, t = threadIdx.x;
    float4* out4 = (float4*)out;
    if (bid < 4096) {                                   // out0 = feat0
        long i4 = (long)bid*1024 + t;
        const float4* s = (const float4*)f0;
        #pragma unroll
        for (int j = 0; j < 4; j++, i4 += 256) out4[i4] = s[i4];
        return;
    }
    if (bid < 6144) {                                   // out1 = feat1
        long i4 = (long)bid*1024 + t;
        const float4* s = (const float4*)f1;
        #pragma unroll
        for (int j = 0; j < 4; j++, i4 += 256) out4[i4] = s[i4 - OFF1/4];
        return;
    }
    long o4 = (long)(bid - 6144)*1024 + t;              // out2 region
    #pragma unroll
    for (int j = 0; j < 4; j++, o4 += 256) {
        int b   = (int)(o4 >> 18);                      // 262144 float4/batch
        int rem = (int)(o4 & 262143);
        int c   = rem >> 8;
        int p   = (rem & 255)*4;
        float4 v = ((const float4*)f2)[o4];
        int4 mm = *(const int4*)(g_idx + b*P2 + p);
        float* vv = (float*)&v;
        int mmv[4] = {mm.x, mm.y, mm.z, mm.w};
        #pragma unroll
        for (int q = 0; q < 4; q++) {
            int m = mmv[q];
            if (m >= 0) {
                long a = (long)(b*NM + m)*C2 + c;
                vv[q] += g_mf0[a] + g_scale[b*NM + m]*g_gp[a];
            }
        }
        out4[OFF2/4 + o4] = v;
    }
}

extern "C" void kernel_launch(void* const* d_in, const int* in_sizes, int n_in,
                              void* d_out, int out_size) {
    // Resolve inputs by unique element counts (robust to metadata ordering).
    const float* f0 = 0; const float* f1 = 0; const float* f2 = 0;
    const int* sam = 0; const float* W2 = 0; const float* b2 = 0;
    const float* g2 = 0;
    for (int i = 0; i < n_in; i++) {
        switch (in_sizes[i]) {
            case 16777216: f0  = (const float*)d_in[i]; break;  // 4*256*128*128
            case 8388608:  f1  = (const float*)d_in[i]; break;  // 4*512*64*64
            case 4194304:  f2  = (const float*)d_in[i]; break;  // 4*1024*32*32
            case 34603008: sam = (const int*)d_in[i];   break;  // 4*33*512*512
            case 1048576:  W2  = (const float*)d_in[i]; break;  // 1024*1024
            case 1024:     b2  = (const float*)d_in[i]; break;  // bias2
            case 1: if (!g2) g2 = (const float*)d_in[i]; break; // gates all equal
            default: break;
        }
    }
    float* out = (float*)d_out;

    k_mfpart <<<dim3(NB,4,NPC), 256>>>(sam, f2);
    k_qgemm  <<<dim3(16,KS), 256>>>(W2);
    k_qreduce<<<NR, 256>>>(b2);
    k_attn2  <<<dim3(NB,NM), 1024>>>(g2);
    k_final  <<<7168, 256>>>(f0, f1, f2, out);
}

// round 17
// speedup vs baseline: 1.1570x; 1.1570x over previous
#include <cuda_runtime.h>
#include <math.h>
#include <mma.h>

using namespace nvcuda;

// Problem constants
#define NB 4          // batch
#define NM 32         // masks (sam_masks[:,1:])
#define C2 1024       // channels of layer 2
#define P2 1024       // 32*32 pixels of layer 2
#define HMASK 512     // sam mask resolution
#define NR 128        // NB*NM rows
#define KS 16         // K-splits in qgemm (KC=64)
#define NPC 8         // pixel chunks in pooling (128 px each)

// Output layout: out0 | out1 | out2 (floats)
#define OFF1 16777216L   // 4*256*128*128
#define OFF2 25165824L   // OFF1 + 4*512*64*64
#define TOT  29360128L   // OFF2 + 4*1024*32*32

// qgemm smem: A[128][68] + B[128][68] tf32, dynamic
#define ALD 68
#define QG_SMEM (2*128*ALD*4)   // 69632 bytes

// -------- scratch (device globals; no allocation allowed) --------
__device__ int   g_idx[NB*P2];             // mask id per sampled pixel, -1 if none
__device__ float g_mfpart[NB*NPC*NM*C2];   // raw pooling partials (4MB, L2)
__device__ float g_mf0[NR*C2];             // normalized mask features (= mf' * beta)
__device__ float g_qpart[KS*NR*C2];        // q GEMM K-split partials (8MB)
__device__ float g_q[NR*C2];               // q = beta*(mf' @ W^T) + b
__device__ float g_qn[NR];                 // ||q_row||
__device__ float g_gp[NR*C2];              // graph-attn output (unnormalized)
__device__ float g_scale[NR];              // sigmoid(g)/max(||gp||,1e-12)

// -------- K1: pooling with FUSED idx computation --------
__global__ void k_mfpart(const int* __restrict__ sam,
                         const float* __restrict__ feat2) {
    int b = blockIdx.x, ct = blockIdx.y, pc = blockIdx.z;  // (4,4,8)
    int t = threadIdx.x;                 // 256, thread = one channel
    int c = ct*256 + t;
    __shared__ float sbins[NM*256];      // [m*256+t]: bank = t%32, conflict-free
    __shared__ int   sidx[128];
    #pragma unroll
    for (int m = 0; m < NM; m++) sbins[m*256 + t] = 0.f;
    if (t < 128) sidx[t] = -1;
    __syncthreads();
    // idx for the 128 pixels of this chunk (shared atomicMax = deterministic)
    #pragma unroll
    for (int i = 0; i < 16; i++) {
        int task = i*256 + t;            // p = task&127, m = task>>7
        int p = task & 127, m = task >> 7;
        int pix = pc*128 + p;
        int y = pix >> 5, x = pix & 31;
        long off = ((long)b*33 + (m+1))*HMASK*HMASK + (long)(y*16)*HMASK + (long)(x*16);
        if (__ldg(sam + off) == 1) atomicMax(&sidx[p], m);
    }
    __syncthreads();
    if (ct == 0 && t < 128) g_idx[b*P2 + pc*128 + t] = sidx[t];
    const float4* fp = (const float4*)(feat2 + ((long)b*C2 + c)*P2 + pc*128);
    #pragma unroll 4
    for (int i = 0; i < 32; i++) {
        float4 v = fp[i];
        int p0 = i*4;
        int m0 = sidx[p0+0], m1 = sidx[p0+1], m2 = sidx[p0+2], m3 = sidx[p0+3];
        if (m0 >= 0) sbins[m0*256 + t] += v.x;
        if (m1 >= 0) sbins[m1*256 + t] += v.y;
        if (m2 >= 0) sbins[m2*256 + t] += v.z;
        if (m3 >= 0) sbins[m3*256 + t] += v.w;
    }
    #pragma unroll
    for (int m = 0; m < NM; m++)
        g_mfpart[((b*NPC + pc)*NM + m)*C2 + c] = sbins[m*256 + t];
}

// -------- K2: TF32 wmma qgemm, BOTH operands smem-staged (coalesced) -------
// grid (8 cb, 16 ks) = 128 blocks x 256 thr (8 warps). Block computes
// 128 rows x 128 cols x 64 K. Warp w owns rows [w*16, w*16+16) x all 128 cols.
__global__ void __launch_bounds__(256)
k_qgemm(const float* __restrict__ W) {
    extern __shared__ float smem[];
    float* sA = smem;                      // [128][ALD] tf32 (rows x k)
    float* sB = smem + 128*ALD;            // [128][ALD] tf32 (cols x k)
    int cb = blockIdx.x, ks = blockIdx.y;
    int t = threadIdx.x;
    int w = t >> 5;                        // 8 warps
    int k0 = ks*64;
    // stage A: mf'[row][k0..k0+63] = sum of 8 partials; 128x16 k4-tasks
    #pragma unroll
    for (int it = 0; it < 8; it++) {
        int task = it*256 + t;
        int row = task & 127, k4 = task >> 7;
        int bb = row >> 5, mm = row & 31;
        float4 v = make_float4(0.f, 0.f, 0.f, 0.f);
        #pragma unroll
        for (int pc = 0; pc < NPC; pc++) {
            float4 p = *(const float4*)(g_mfpart + ((long)(bb*NPC + pc)*NM + mm)*C2 + k0 + k4*4);
            v.x += p.x; v.y += p.y; v.z += p.z; v.w += p.w;
        }
        float* d = sA + row*ALD + k4*4;
        d[0] = wmma::__float_to_tf32(v.x);
        d[1] = wmma::__float_to_tf32(v.y);
        d[2] = wmma::__float_to_tf32(v.z);
        d[3] = wmma::__float_to_tf32(v.w);
    }
    // stage B: W[cb*128+c][k0..k0+63], coalesced float4 rows
    #pragma unroll
    for (int it = 0; it < 8; it++) {
        int task = it*256 + t;
        int c = task & 127, k4 = task >> 7;
        float4 ww = *(const float4*)(W + (long)(cb*128 + c)*C2 + k0 + k4*4);
        float* d = sB + c*ALD + k4*4;
        d[0] = wmma::__float_to_tf32(ww.x);
        d[1] = wmma::__float_to_tf32(ww.y);
        d[2] = wmma::__float_to_tf32(ww.z);
        d[3] = wmma::__float_to_tf32(ww.w);
    }
    __syncthreads();
    wmma::fragment<wmma::accumulator, 16, 16, 8, float> fc[8];
    #pragma unroll
    for (int n = 0; n < 8; n++) wmma::fill_fragment(fc[n], 0.f);
    int row0 = w*16;
    #pragma unroll
    for (int kk = 0; kk < 64; kk += 8) {
        wmma::fragment<wmma::matrix_a, 16, 16, 8, wmma::precision::tf32, wmma::row_major> fa;
        wmma::load_matrix_sync(fa, sA + row0*ALD + kk, ALD);
        #pragma unroll
        for (int n = 0; n < 8; n++) {
            // B col_major: element (k, col) at sB[(n*16+col)*ALD + kk + k]
            wmma::fragment<wmma::matrix_b, 16, 16, 8, wmma::precision::tf32, wmma::col_major> fb;
            wmma::load_matrix_sync(fb, sB + (n*16)*ALD + kk, ALD);
            wmma::mma_sync(fc[n], fa, fb, fc[n]);
        }
    }
    #pragma unroll
    for (int n = 0; n < 8; n++)
        wmma::store_matrix_sync(g_qpart + ((long)ks*NR + row0)*C2 + cb*128 + n*16,
                                fc[n], C2, wmma::mem_row_major);
}

// -------- K3: per-row cnt, beta, mf0, q = beta*sum(qpart)+bias, qn --------
__global__ void k_qreduce(const float* __restrict__ bias) {
    int row = blockIdx.x, t = threadIdx.x;   // 128 blocks x 256
    int b = row >> 5, m = row & 31;
    int w = t >> 5, l = t & 31;
    __shared__ float sw8[8];
    const int* ip = g_idx + b*P2;
    int cnt = 0;
    #pragma unroll
    for (int j = 0; j < 4; j++) cnt += (ip[t + j*256] == m);
    float fc = (float)cnt;
    #pragma unroll
    for (int o = 16; o; o >>= 1) fc += __shfl_xor_sync(0xffffffffu, fc, o);
    if (l == 0) sw8[w] = fc;
    __syncthreads();
    float tot = 0.f;
    #pragma unroll
    for (int i = 0; i < 8; i++) tot += sw8[i];
    float inv = 1.f / (tot + 1e-5f);
    __syncthreads();
    float mfv[4]; float sq = 0.f;
    #pragma unroll
    for (int j = 0; j < 4; j++) {
        int c = t + j*256;
        float v = 0.f;
        #pragma unroll
        for (int pc = 0; pc < NPC; pc++)
            v += g_mfpart[((long)(b*NPC + pc)*NM + m)*C2 + c];
        mfv[j] = v;
        sq += v*v;
    }
    #pragma unroll
    for (int o = 16; o; o >>= 1) sq += __shfl_xor_sync(0xffffffffu, sq, o);
    if (l == 0) sw8[w] = sq;
    __syncthreads();
    float s2 = 0.f;
    #pragma unroll
    for (int i = 0; i < 8; i++) s2 += sw8[i];
    float beta = inv / fmaxf(inv*sqrtf(s2), 1e-12f);   // exact l2norm algebra
    __syncthreads();
    float sqq = 0.f;
    #pragma unroll
    for (int j = 0; j < 4; j++) {
        int c = t + j*256;
        g_mf0[(long)row*C2 + c] = mfv[j]*beta;
        float v = 0.f;
        #pragma unroll
        for (int ks = 0; ks < KS; ks++)
            v += g_qpart[((long)ks*NR + row)*C2 + c];
        v = beta*v + bias[c];
        sqq += v*v;
        g_q[(long)row*C2 + c] = v;
    }
    #pragma unroll
    for (int o = 16; o; o >>= 1) sqq += __shfl_xor_sync(0xffffffffu, sqq, o);
    if (l == 0) sw8[w] = sqq;
    __syncthreads();
    if (t == 0) {
        float n2 = 0.f;
        #pragma unroll
        for (int i = 0; i < 8; i++) n2 += sw8[i];
        g_qn[row] = sqrtf(n2);
    }
}

// -------- K4: fused edge row + gp row + gate scale. 1024 threads/block -----
__global__ void __launch_bounds__(1024)
k_attn2(const float* __restrict__ gate) {
    int b = blockIdx.x, i = blockIdx.y, t = threadIdx.x;
    int w = t >> 5, l = t & 31;                 // 32 warps
    __shared__ float sdot[NM];
    __shared__ float se[NM];
    __shared__ float sw32[32];
    {
        const float4* qi = (const float4*)(g_q + (long)(b*NM + i)*C2);
        const float4* qj = (const float4*)(g_q + (long)(b*NM + w)*C2);
        float part = 0.f;
        #pragma unroll
        for (int k = 0; k < 8; k++) {
            float4 a = qi[k*32 + l], bb = qj[k*32 + l];
            part += a.x*bb.x + a.y*bb.y + a.z*bb.z + a.w*bb.w;
        }
        #pragma unroll
        for (int o = 16; o; o >>= 1) part += __shfl_xor_sync(0xffffffffu, part, o);
        if (l == 0) sdot[w] = part;
    }
    __syncthreads();
    if (t < NM) {
        float sim = sdot[t] / (g_qn[b*NM + i]*g_qn[b*NM + t] + 1e-8f);
        float rs = sim;
        #pragma unroll
        for (int o = 16; o; o >>= 1) rs += __shfl_xor_sync(0xffffffffu, rs, o);
        se[t] = sim / (rs + 1e-8f);
    }
    __syncthreads();
    float acc = 0.f;
    #pragma unroll 8
    for (int n = 0; n < NM; n++)
        acc += se[n] * g_q[(long)(b*NM + n)*C2 + t];
    g_gp[(long)(b*NM + i)*C2 + t] = acc;
    float sq = acc*acc;
    #pragma unroll
    for (int o = 16; o; o >>= 1) sq += __shfl_xor_sync(0xffffffffu, sq, o);
    if (l == 0) sw32[w] = sq;
    __syncthreads();
    if (t == 0) {
        float s2 = 0.f;
        #pragma unroll
        for (int k = 0; k < 32; k++) s2 += sw32[k];   // fixed order
        float sg = 1.f / (1.f + expf(-gate[0]));
        g_scale[b*NM + i] = sg / fmaxf(sqrtf(s2), 1e-12f);
    }
}

// -------- K5: copies + out2 gather; ILP-4, block-uniform region branch -----
__global__ void k_final(const float* __restrict__ f0,
                        const float* __restrict__ f1,
                        const float* __restrict__ f2,
                        float* __restrict__ out) {
    int bid = blockIdx.x, t = threadIdx.x;
    float4* out4 = (float4*)out;
    if (bid < 4096) {                                   // out0 = feat0
        long i4 = (long)bid*1024 + t;
        const float4* s = (const float4*)f0;
        #pragma unroll
        for (int j = 0; j < 4; j++, i4 += 256) out4[i4] = s[i4];
        return;
    }
    if (bid < 6144) {                                   // out1 = feat1
        long i4 = (long)bid*1024 + t;
        const float4* s = (const float4*)f1;
        #pragma unroll
        for (int j = 0; j < 4; j++, i4 += 256) out4[i4] = s[i4 - OFF1/4];
        return;
    }
    long o4 = (long)(bid - 6144)*1024 + t;              // out2 region
    #pragma unroll
    for (int j = 0; j < 4; j++, o4 += 256) {
        int b   = (int)(o4 >> 18);                      // 262144 float4/batch
        int rem = (int)(o4 & 262143);
        int c   = rem >> 8;
        int p   = (rem & 255)*4;
        float4 v = ((const float4*)f2)[o4];
        int4 mm = *(const int4*)(g_idx + b*P2 + p);
        float* vv = (float*)&v;
        int mmv[4] = {mm.x, mm.y, mm.z, mm.w};
        #pragma unroll
        for (int q = 0; q < 4; q++) {
            int m = mmv[q];
            if (m >= 0) {
                long a = (long)(b*NM + m)*C2 + c;
                vv[q] += g_mf0[a] + g_scale[b*NM + m]*g_gp[a];
            }
        }
        out4[OFF2/4 + o4] = v;
    }
}

extern "C" void kernel_launch(void* const* d_in, const int* in_sizes, int n_in,
                              void* d_out, int out_size) {
    // Resolve inputs by unique element counts (robust to metadata ordering).
    const float* f0 = 0; const float* f1 = 0; const float* f2 = 0;
    const int* sam = 0; const float* W2 = 0; const float* b2 = 0;
    const float* g2 = 0;
    for (int i = 0; i < n_in; i++) {
        switch (in_sizes[i]) {
            case 16777216: f0  = (const float*)d_in[i]; break;  // 4*256*128*128
            case 8388608:  f1  = (const float*)d_in[i]; break;  // 4*512*64*64
            case 4194304:  f2  = (const float*)d_in[i]; break;  // 4*1024*32*32
            case 34603008: sam = (const int*)d_in[i];   break;  // 4*33*512*512
            case 1048576:  W2  = (const float*)d_in[i]; break;  // 1024*1024
            case 1024:     b2  = (const float*)d_in[i]; break;  // bias2
            case 1: if (!g2) g2 = (const float*)d_in[i]; break; // gates all equal
            default: break;
        }
    }
    float* out = (float*)d_out;

    // Opt-in to >48KB dynamic smem for the wmma GEMM (attribute set, no alloc;
    // idempotent and capture-safe).
    cudaFuncSetAttribute(k_qgemm, cudaFuncAttributeMaxDynamicSharedMemorySize,
                         QG_SMEM);

    k_mfpart <<<dim3(NB,4,NPC), 256>>>(sam, f2);
    k_qgemm  <<<dim3(8,KS), 256, QG_SMEM>>>(W2);
    k_qreduce<<<NR, 256>>>(b2);
    k_attn2  <<<dim3(NB,NM), 1024>>>(g2);
    k_final  <<<7168, 256>>>(f0, f1, f2, out);
}